// round 1
// baseline (speedup 1.0000x reference)
#include <cuda_runtime.h>

// ---------------- problem constants (fixed by dataset) ----------------
#define NNODES 100000
#define NEDGES 1600000
#define DH 128           // feature dim (D == H)
#define NG 512           // num graphs
#define NL 5             // total reps (input + 4 layers)
#define NLG 4            // GIN layers
#define OO 64            // output dim
#define BN_EPS 1e-5f

// ---------------- static device scratch (no allocations allowed) ------
__device__ float g_hidden[NLG][(size_t)NNODES * DH];  // h1..h4
__device__ float g_pooled[(size_t)NNODES * DH];
__device__ float g_y1[(size_t)NNODES * DH];
__device__ float g_z[(size_t)NNODES * DH];
__device__ int   g_deg[NNODES];
__device__ int   g_off[NNODES + 1];
__device__ int   g_cursor[NNODES];
__device__ int   g_srcs[NEDGES];
__device__ int   g_gstart[NG + 1];
__device__ float g_stats[NLG][2][2 * DH];   // [layer][stage][sum(128) | sumsq(128)]
__device__ float g_ph[NL][NG * DH];         // per-graph pooled reps

// ---------------- small utility kernels --------------------------------
__global__ void zero_kernel(int n_nodes) {
    int i = blockIdx.x * blockDim.x + threadIdx.x;
    if (i < n_nodes) g_deg[i] = 0;
    if (i < NLG * 2 * 2 * DH) ((float*)g_stats)[i] = 0.0f;
}

__global__ void hist_kernel(const int* __restrict__ dst, int E) {
    int i = blockIdx.x * blockDim.x + threadIdx.x;
    if (i < E) atomicAdd(&g_deg[dst[i]], 1);
}

// single-block exclusive scan of g_deg -> g_off (and g_cursor copy)
__global__ void scan_kernel(int n) {
    __shared__ int warpsum[32];
    __shared__ int carry_s;
    int tid = threadIdx.x, lane = tid & 31, wid = tid >> 5;
    if (tid == 0) carry_s = 0;
    __syncthreads();
    for (int base = 0; base < n; base += 1024) {
        int i = base + tid;
        int v = (i < n) ? g_deg[i] : 0;
        int xv = v;
        #pragma unroll
        for (int o = 1; o < 32; o <<= 1) {
            int t = __shfl_up_sync(0xffffffffu, xv, o);
            if (lane >= o) xv += t;
        }
        if (lane == 31) warpsum[wid] = xv;
        __syncthreads();
        if (wid == 0) {
            int w = warpsum[lane];
            int yv = w;
            #pragma unroll
            for (int o = 1; o < 32; o <<= 1) {
                int t = __shfl_up_sync(0xffffffffu, yv, o);
                if (lane >= o) yv += t;
            }
            warpsum[lane] = yv - w;  // exclusive prefix of warp sums
        }
        __syncthreads();
        int excl = carry_s + warpsum[wid] + xv - v;
        if (i < n) { g_off[i] = excl; g_cursor[i] = excl; }
        __syncthreads();
        if (tid == 1023) carry_s += warpsum[31] + xv;
        __syncthreads();
    }
    if (tid == 0) g_off[n] = carry_s;
}

__global__ void scatter_kernel(const int* __restrict__ src,
                               const int* __restrict__ dst, int E) {
    int i = blockIdx.x * blockDim.x + threadIdx.x;
    if (i < E) {
        int p = atomicAdd(&g_cursor[dst[i]], 1);
        g_srcs[p] = src[i];
    }
}

// graph boundaries from sorted graph_ids
__global__ void gbounds_kernel(const int* __restrict__ gid, int n) {
    int i = blockIdx.x * blockDim.x + threadIdx.x;
    if (i > n) return;
    if (i == 0) {
        int b = gid[0];
        for (int g = 0; g <= b; ++g) g_gstart[g] = 0;
    } else if (i == n) {
        int a = gid[n - 1];
        for (int g = a + 1; g <= NG; ++g) g_gstart[g] = n;
    } else {
        int a = gid[i - 1], b = gid[i];
        for (int g = a + 1; g <= b; ++g) g_gstart[g] = i;
    }
}

// ---------------- aggregation: warp per node, CSR gather ---------------
__global__ void agg_kernel(const float* __restrict__ h,
                           const float* __restrict__ eps, int l, int n) {
    int w = (blockIdx.x * blockDim.x + threadIdx.x) >> 5;
    if (w >= n) return;
    int lane = threadIdx.x & 31;
    float onepe = 1.0f + __ldg(&eps[l]);
    const float4* hv = (const float4*)h;
    float4 acc = __ldg(&hv[(size_t)w * 32 + lane]);
    acc.x *= onepe; acc.y *= onepe; acc.z *= onepe; acc.w *= onepe;
    int s = g_off[w], e = g_off[w + 1];
    int j = s;
    for (; j + 4 <= e; j += 4) {
        int s0 = g_srcs[j], s1 = g_srcs[j + 1], s2 = g_srcs[j + 2], s3 = g_srcs[j + 3];
        float4 v0 = __ldg(&hv[(size_t)s0 * 32 + lane]);
        float4 v1 = __ldg(&hv[(size_t)s1 * 32 + lane]);
        float4 v2 = __ldg(&hv[(size_t)s2 * 32 + lane]);
        float4 v3 = __ldg(&hv[(size_t)s3 * 32 + lane]);
        acc.x += (v0.x + v1.x) + (v2.x + v3.x);
        acc.y += (v0.y + v1.y) + (v2.y + v3.y);
        acc.z += (v0.z + v1.z) + (v2.z + v3.z);
        acc.w += (v0.w + v1.w) + (v2.w + v3.w);
    }
    for (; j < e; ++j) {
        int s0 = g_srcs[j];
        float4 v0 = __ldg(&hv[(size_t)s0 * 32 + lane]);
        acc.x += v0.x; acc.y += v0.y; acc.z += v0.z; acc.w += v0.w;
    }
    ((float4*)g_pooled)[(size_t)w * 32 + lane] = acc;
}

// ---------------- fused GEMM (+optional pre-BN/ReLU on A, +col stats) --
// C[M,128] = f(A)[M,128] @ W[128,128] + bias ; accumulate col sum/sumsq
template <bool PRE_BN>
__global__ void __launch_bounds__(256, 2)
gemm_kernel(const float* __restrict__ A, const float* __restrict__ W,
            const float* __restrict__ bias,
            const float* __restrict__ gamma, const float* __restrict__ beta,
            float* __restrict__ C, int l, int M) {
    __shared__ float As[8][132];
    __shared__ float Ws[8][128];
    __shared__ float s_scale[128], s_shift[128];
    __shared__ float s_sum[128], s_sq[128];
    int tid = threadIdx.x;
    if (PRE_BN) {
        if (tid < 128) {
            float inv = 1.0f / (float)M;
            float su = g_stats[l][0][tid], sq = g_stats[l][0][128 + tid];
            float m = su * inv;
            float v = sq * inv - m * m;
            float s = __ldg(&gamma[tid]) * rsqrtf(v + BN_EPS);
            s_scale[tid] = s;
            s_shift[tid] = __ldg(&beta[tid]) - m * s;
        }
    }
    if (tid < 128) { s_sum[tid] = 0.0f; s_sq[tid] = 0.0f; }
    __syncthreads();

    int row0 = blockIdx.x * 128;
    int tx = tid & 15, ty = tid >> 4;
    int arow = tid >> 1, acol = (tid & 1) * 4;
    int wrow = tid >> 5, wcol = (tid & 31) * 4;
    int grow = row0 + arow;
    bool aval = (grow < M);
    const float* Aptr = A + (size_t)grow * 128 + acol;
    const float* Wptr = W + (size_t)wrow * 128 + wcol;

    float acc[8][8];
    #pragma unroll
    for (int i = 0; i < 8; ++i)
        #pragma unroll
        for (int j = 0; j < 8; ++j) acc[i][j] = 0.0f;

    for (int kb = 0; kb < 128; kb += 8) {
        float4 av = aval ? *(const float4*)(Aptr + kb) : make_float4(0, 0, 0, 0);
        float4 wv = *(const float4*)(Wptr + (size_t)kb * 128);
        if (PRE_BN && aval) {
            int c = kb + acol;
            av.x = fmaxf(fmaf(av.x, s_scale[c + 0], s_shift[c + 0]), 0.0f);
            av.y = fmaxf(fmaf(av.y, s_scale[c + 1], s_shift[c + 1]), 0.0f);
            av.z = fmaxf(fmaf(av.z, s_scale[c + 2], s_shift[c + 2]), 0.0f);
            av.w = fmaxf(fmaf(av.w, s_scale[c + 3], s_shift[c + 3]), 0.0f);
        }
        __syncthreads();
        As[acol + 0][arow] = av.x;
        As[acol + 1][arow] = av.y;
        As[acol + 2][arow] = av.z;
        As[acol + 3][arow] = av.w;
        *(float4*)&Ws[wrow][wcol] = wv;
        __syncthreads();
        #pragma unroll
        for (int k = 0; k < 8; ++k) {
            float a[8], b[8];
            *(float4*)&a[0] = *(const float4*)&As[k][ty * 8];
            *(float4*)&a[4] = *(const float4*)&As[k][ty * 8 + 4];
            *(float4*)&b[0] = *(const float4*)&Ws[k][tx * 8];
            *(float4*)&b[4] = *(const float4*)&Ws[k][tx * 8 + 4];
            #pragma unroll
            for (int i = 0; i < 8; ++i)
                #pragma unroll
                for (int j = 0; j < 8; ++j)
                    acc[i][j] = fmaf(a[i], b[j], acc[i][j]);
        }
    }

    float bcol[8];
    #pragma unroll
    for (int j = 0; j < 8; ++j) bcol[j] = __ldg(&bias[tx * 8 + j]);
    float psum[8], psq[8];
    #pragma unroll
    for (int j = 0; j < 8; ++j) { psum[j] = 0.0f; psq[j] = 0.0f; }
    #pragma unroll
    for (int i = 0; i < 8; ++i) {
        int gr = row0 + ty * 8 + i;
        if (gr < M) {
            float v[8];
            #pragma unroll
            for (int j = 0; j < 8; ++j) {
                v[j] = acc[i][j] + bcol[j];
                psum[j] += v[j];
                psq[j]  += v[j] * v[j];
            }
            float4 o0 = make_float4(v[0], v[1], v[2], v[3]);
            float4 o1 = make_float4(v[4], v[5], v[6], v[7]);
            *(float4*)&C[(size_t)gr * 128 + tx * 8]     = o0;
            *(float4*)&C[(size_t)gr * 128 + tx * 8 + 4] = o1;
        }
    }
    #pragma unroll
    for (int j = 0; j < 8; ++j) {
        atomicAdd(&s_sum[tx * 8 + j], psum[j]);
        atomicAdd(&s_sq[tx * 8 + j], psq[j]);
    }
    __syncthreads();
    const int stage = PRE_BN ? 1 : 0;
    if (tid < 128) {
        atomicAdd(&g_stats[l][stage][tid], s_sum[tid]);
        atomicAdd(&g_stats[l][stage][128 + tid], s_sq[tid]);
    }
}

// ---------------- outer BN + ReLU, writes hidden rep -------------------
__global__ void finish_kernel(const float* __restrict__ z,
                              const float* __restrict__ gamma,
                              const float* __restrict__ beta,
                              float* __restrict__ hout, int l, int M) {
    __shared__ float s_scale[128], s_shift[128];
    int tid = threadIdx.x;
    if (tid < 128) {
        float inv = 1.0f / (float)M;
        float m = g_stats[l][1][tid] * inv;
        float v = g_stats[l][1][128 + tid] * inv - m * m;
        float s = __ldg(&gamma[tid]) * rsqrtf(v + BN_EPS);
        s_scale[tid] = s;
        s_shift[tid] = __ldg(&beta[tid]) - m * s;
    }
    __syncthreads();
    int idx = blockIdx.x * blockDim.x + tid;  // float4 index
    if (idx < M * 32) {
        int c = (idx & 31) * 4;
        float4 v = ((const float4*)z)[idx];
        float4 o;
        o.x = fmaxf(fmaf(v.x, s_scale[c + 0], s_shift[c + 0]), 0.0f);
        o.y = fmaxf(fmaf(v.y, s_scale[c + 1], s_shift[c + 1]), 0.0f);
        o.z = fmaxf(fmaf(v.z, s_scale[c + 2], s_shift[c + 2]), 0.0f);
        o.w = fmaxf(fmaf(v.w, s_scale[c + 3], s_shift[c + 3]), 0.0f);
        ((float4*)hout)[idx] = o;
    }
}

// ---------------- per-graph segmented pooling of all 5 reps ------------
__global__ void pool_kernel(const float* __restrict__ x) {
    int g = blockIdx.x, l = blockIdx.y, c = threadIdx.x;
    const float* h = (l == 0) ? x : &g_hidden[l - 1][0];
    int s = g_gstart[g], e = g_gstart[g + 1];
    float acc = 0.0f;
    int r = s;
    for (; r + 4 <= e; r += 4) {
        acc += __ldg(&h[(size_t)(r + 0) * DH + c]);
        acc += __ldg(&h[(size_t)(r + 1) * DH + c]);
        acc += __ldg(&h[(size_t)(r + 2) * DH + c]);
        acc += __ldg(&h[(size_t)(r + 3) * DH + c]);
    }
    for (; r < e; ++r) acc += __ldg(&h[(size_t)r * DH + c]);
    g_ph[l][g * DH + c] = acc;
}

// ---------------- final score: 512 x 64 --------------------------------
__global__ void score_kernel(const float* __restrict__ Wp,
                             const float* __restrict__ bp,
                             float* __restrict__ out) {
    int g = blockIdx.x;
    __shared__ float sph[NL * DH];
    for (int i = threadIdx.x; i < NL * DH; i += blockDim.x) {
        int l = i / DH, c = i % DH;
        sph[i] = g_ph[l][g * DH + c];
    }
    __syncthreads();
    int o = threadIdx.x;  // 64 threads
    float acc = 0.0f;
    for (int l = 0; l < NL; ++l) {
        acc += __ldg(&bp[l * OO + o]);
        const float* Wl = Wp + (size_t)l * DH * OO;
        #pragma unroll 4
        for (int c = 0; c < DH; ++c)
            acc = fmaf(sph[l * DH + c], __ldg(&Wl[c * OO + o]), acc);
    }
    out[g * OO + o] = acc;
}

// ---------------- launcher ---------------------------------------------
extern "C" void kernel_launch(void* const* d_in, const int* in_sizes, int n_in,
                              void* d_out, int out_size) {
    const float* x   = (const float*)d_in[0];
    const int*   src = (const int*)d_in[1];
    const int*   dst = (const int*)d_in[2];
    const int*   gid = (const int*)d_in[3];
    // d_in[4] = num_graphs (device scalar, value fixed = 512)
    const float* eps = (const float*)d_in[5];
    const float* W1  = (const float*)d_in[6];
    const float* b1  = (const float*)d_in[7];
    const float* gm  = (const float*)d_in[8];
    const float* bm  = (const float*)d_in[9];
    const float* W2  = (const float*)d_in[10];
    const float* b2  = (const float*)d_in[11];
    const float* go  = (const float*)d_in[12];
    const float* bo  = (const float*)d_in[13];
    const float* Wp  = (const float*)d_in[14];
    const float* bp  = (const float*)d_in[15];
    float* out = (float*)d_out;

    int N = in_sizes[0] / DH;   // 100000
    int E = in_sizes[1];        // 1600000

    float *pooled, *y1, *z, *hid;
    cudaGetSymbolAddress((void**)&pooled, g_pooled);
    cudaGetSymbolAddress((void**)&y1, g_y1);
    cudaGetSymbolAddress((void**)&z, g_z);
    cudaGetSymbolAddress((void**)&hid, g_hidden);

    zero_kernel<<<(N + 255) / 256, 256>>>(N);
    hist_kernel<<<(E + 255) / 256, 256>>>(dst, E);
    scan_kernel<<<1, 1024>>>(N);
    scatter_kernel<<<(E + 255) / 256, 256>>>(src, dst, E);
    gbounds_kernel<<<(N + 1 + 255) / 256, 256>>>(gid, N);

    int gemmGrid = (N + 127) / 128;
    int elemGrid = (N * 32 + 255) / 256;
    int aggGrid  = (N * 32 + 255) / 256;  // warp per node

    for (int l = 0; l < NLG; ++l) {
        const float* h = (l == 0) ? x : (hid + (size_t)(l - 1) * N * DH);
        agg_kernel<<<aggGrid, 256>>>(h, eps, l, N);
        gemm_kernel<false><<<gemmGrid, 256>>>(pooled, W1 + (size_t)l * DH * DH,
                                              b1 + l * DH, nullptr, nullptr,
                                              y1, l, N);
        gemm_kernel<true><<<gemmGrid, 256>>>(y1, W2 + (size_t)l * DH * DH,
                                             b2 + l * DH, gm + l * DH, bm + l * DH,
                                             z, l, N);
        finish_kernel<<<elemGrid, 256>>>(z, go + l * DH, bo + l * DH,
                                         hid + (size_t)l * N * DH, l, N);
    }

    dim3 pg(NG, NL);
    pool_kernel<<<pg, DH>>>(x);
    score_kernel<<<NG, 64>>>(Wp, bp, out);
}